// round 1
// baseline (speedup 1.0000x reference)
#include <cuda_runtime.h>
#include <math.h>

// Shapes (fixed by the problem)
#define BB 64      // batch
#define DD 512     // in dims
#define PP 128     // patches
#define NM 1152    // P*9 mask logits per batch
#define NT 768     // P*6 theta per batch
#define NO 1920    // NM + NT
#define SS 64      // scene size

// GEMM tiling
#define KSPLIT 8
#define KCH 64     // K chunk per block (KSPLIT*KCH == DD)
#define OT 64      // outputs per block (NO/OT = 30 tiles; 1152 is a multiple of 64 so no tile straddles Wm/Wt)

// Static device scratch (no allocations allowed)
__device__ float g_part[KSPLIT][BB * NO];   // 3.93 MB k-split partials
__device__ float g_masks[BB * NM];          // (1-sigmoid)*noise, per (b, p*9+ij)
__device__ float g_theta[BB * NT];          // theta + bias, per (b, p*6+rc)

// ---------------------------------------------------------------------------
// Kernel A: partial GEMM  C[b, o] += z[b, kbase:kbase+64] . W[o, kbase:kbase+64]
// Block: 64 outputs x 64 batches tile, 256 threads, 4x4 register micro-tile.
// grid = (30 output tiles, 8 k-splits) = 240 blocks.
// ---------------------------------------------------------------------------
__global__ __launch_bounds__(256) void gemm_part_kernel(
    const float* __restrict__ z, const float* __restrict__ Wm,
    const float* __restrict__ Wt)
{
    __shared__ float zs[BB][KCH + 1];   // +1 pad: conflict-free column reads
    __shared__ float ws[OT][KCH + 1];

    const int obase = blockIdx.x * OT;
    const int kbase = blockIdx.y * KCH;
    const int tid = threadIdx.x;

    // Stage z tile: 64 batches x 64 k, coalesced rows
    for (int i = tid; i < BB * KCH; i += 256) {
        int b = i >> 6, k = i & 63;
        zs[b][k] = z[b * DD + kbase + k];
    }
    // Stage W tile: 64 outputs x 64 k (Wm rows for o<1152, else Wt rows)
    for (int i = tid; i < OT * KCH; i += 256) {
        int o = i >> 6, k = i & 63;
        int og = obase + o;
        ws[o][k] = (og < NM) ? Wm[og * DD + kbase + k]
                             : Wt[(og - NM) * DD + kbase + k];
    }
    __syncthreads();

    const int tx = tid & 15;   // output lane  -> outputs tx + 16*i  (stride-16: conflict-free)
    const int ty = tid >> 4;   // batch  lane  -> batches ty + 16*j

    float acc[4][4];
#pragma unroll
    for (int i = 0; i < 4; i++)
#pragma unroll
        for (int j = 0; j < 4; j++) acc[i][j] = 0.f;

#pragma unroll 4
    for (int k = 0; k < KCH; k++) {
        float wv[4], zv[4];
#pragma unroll
        for (int i = 0; i < 4; i++) wv[i] = ws[tx + 16 * i][k];
#pragma unroll
        for (int j = 0; j < 4; j++) zv[j] = zs[ty + 16 * j][k];
#pragma unroll
        for (int i = 0; i < 4; i++)
#pragma unroll
            for (int j = 0; j < 4; j++)
                acc[i][j] = fmaf(wv[i], zv[j], acc[i][j]);
    }

    float* part = g_part[blockIdx.y];
#pragma unroll
    for (int j = 0; j < 4; j++) {
        int b = ty + 16 * j;
#pragma unroll
        for (int i = 0; i < 4; i++)
            part[b * NO + obase + tx + 16 * i] = acc[i][j];
    }
}

// ---------------------------------------------------------------------------
// Kernel B: reduce k-split partials + nonlinearity.
//   o <  1152: g_masks = (1 - sigmoid(s + bm[o])) * noise[o % 9]
//   o >= 1152: g_theta = s + bt[o-1152]
// ---------------------------------------------------------------------------
__global__ __launch_bounds__(256) void reduce_nl_kernel(
    const float* __restrict__ bm, const float* __restrict__ bt,
    const float* __restrict__ noise)
{
    int idx = blockIdx.x * 256 + threadIdx.x;
    if (idx >= BB * NO) return;
    float s = 0.f;
#pragma unroll
    for (int kk = 0; kk < KSPLIT; kk++) s += g_part[kk][idx];
    int b = idx / NO;
    int o = idx - b * NO;
    if (o < NM) {
        float v = 1.f - 1.f / (1.f + expf(-(s + bm[o])));
        g_masks[b * NM + o] = v * noise[o % 9];   // noise[(o%9)/3][(o%9)%3] row-major == o%9
    } else {
        int t = o - NM;
        g_theta[b * NT + t] = s + bt[t];
    }
}

// ---------------------------------------------------------------------------
// Kernel C: affine grid + bilinear zero-padded sample of the 3x3 mask.
// One block per (b,p). 256 threads x 16 px (4 float4 stores each).
// Matches torch affine_grid/grid_sample align_corners=False semantics.
// ---------------------------------------------------------------------------
__global__ __launch_bounds__(256) void render_kernel(float* __restrict__ out)
{
    const int bp = blockIdx.x;          // b*128 + p
    const int b = bp >> 7, p = bp & 127;

    __shared__ float sm[9];
    __shared__ float st[6];
    const int tid = threadIdx.x;
    if (tid < 9)       sm[tid]     = g_masks[b * NM + p * 9 + tid];
    else if (tid < 15) st[tid - 9] = g_theta[b * NT + p * 6 + (tid - 9)];
    __syncthreads();

    const float t00 = st[0], t01 = st[1], t02 = st[2];
    const float t10 = st[3], t11 = st[4], t12 = st[5];

    float4* o4 = reinterpret_cast<float4*>(out + (size_t)bp * (SS * SS));

#pragma unroll
    for (int q = tid; q < (SS * SS) / 4; q += 256) {
        const int y  = q >> 4;             // row
        const int xq = (q & 15) << 2;      // first of 4 consecutive cols
        const float cy = (y + 0.5f) * (1.f / 32.f) - 1.f;   // (y+0.5)/64*2-1 (exact pow2)
        const float gxc = fmaf(t01, cy, t02);
        const float gyc = fmaf(t11, cy, t12);
        float4 r;
        float* rp = &r.x;
#pragma unroll
        for (int d = 0; d < 4; d++) {
            const float cx = (xq + d + 0.5f) * (1.f / 32.f) - 1.f;
            const float gx = fmaf(t00, cx, gxc);
            const float gy = fmaf(t10, cx, gyc);
            const float ix = fmaf(1.5f, gx, 1.f);   // ((gx+1)*3-1)*0.5
            const float iy = fmaf(1.5f, gy, 1.f);
            const float fx = floorf(ix), fy = floorf(iy);
            const float wx1 = ix - fx, wy1 = iy - fy;
            const float wx0 = 1.f - wx1, wy0 = 1.f - wy1;
            const int x0 = (int)fx, y0 = (int)fy;
            const int x1 = x0 + 1,  y1 = y0 + 1;
            const float v00 = ((unsigned)x0 < 3u && (unsigned)y0 < 3u) ? sm[y0 * 3 + x0] : 0.f;
            const float v01 = ((unsigned)x1 < 3u && (unsigned)y0 < 3u) ? sm[y0 * 3 + x1] : 0.f;
            const float v10 = ((unsigned)x0 < 3u && (unsigned)y1 < 3u) ? sm[y1 * 3 + x0] : 0.f;
            const float v11 = ((unsigned)x1 < 3u && (unsigned)y1 < 3u) ? sm[y1 * 3 + x1] : 0.f;
            rp[d] = wy0 * (wx0 * v00 + wx1 * v01) + wy1 * (wx0 * v10 + wx1 * v11);
        }
        o4[q] = r;
    }
}

extern "C" void kernel_launch(void* const* d_in, const int* in_sizes, int n_in,
                              void* d_out, int out_size)
{
    const float* z     = (const float*)d_in[0];
    const float* Wm    = (const float*)d_in[1];
    const float* bm    = (const float*)d_in[2];
    const float* Wt    = (const float*)d_in[3];
    const float* bt    = (const float*)d_in[4];
    const float* noise = (const float*)d_in[5];
    float* out = (float*)d_out;

    gemm_part_kernel<<<dim3(NO / OT, KSPLIT), 256>>>(z, Wm, Wt);
    reduce_nl_kernel<<<(BB * NO + 255) / 256, 256>>>(bm, bt, noise);
    render_kernel<<<BB * PP, 256>>>(out);
}

// round 2
// speedup vs baseline: 1.2984x; 1.2984x over previous
#include <cuda_runtime.h>
#include <math.h>

// Shapes (fixed by the problem)
#define BB 64      // batch
#define DD 512     // in dims
#define PP 128     // patches
#define NM 1152    // P*9 mask logits per batch
#define NT 768     // P*6 theta per batch
#define NO 1920    // NM + NT
#define SS 64      // scene size

// GEMM tiling
#define KSPLIT 16
#define KCH 32     // K chunk per block (KSPLIT*KCH == DD)
#define OT 64      // outputs per block; 1152 % 64 == 0 so no tile straddles Wm/Wt
#define PAD 4      // row pad (floats) -> row stride 36 floats = 144B (16B aligned)

// Static device scratch (no allocations allowed)
__device__ float g_part[KSPLIT][BB * NO];   // 7.86 MB k-split partials (L2-resident)

// ---------------------------------------------------------------------------
// Kernel A: partial GEMM  C[b, o] = z[b, kbase:+32] . W[o, kbase:+32]
// Block: 64 outputs x 64 batches, 256 threads, 4x4 micro-tile, K-vectorized
// float4 shared loads. grid = (30 output tiles, 16 k-splits) = 480 blocks.
// ---------------------------------------------------------------------------
__global__ __launch_bounds__(256) void gemm_part_kernel(
    const float* __restrict__ z, const float* __restrict__ Wm,
    const float* __restrict__ Wt)
{
    __shared__ float zs[BB][KCH + PAD];
    __shared__ float ws[OT][KCH + PAD];

    const int obase = blockIdx.x * OT;
    const int kbase = blockIdx.y * KCH;
    const int tid = threadIdx.x;

    // Stage z tile: 64 rows x 8 float4, coalesced
    for (int i = tid; i < BB * (KCH / 4); i += 256) {
        int b = i >> 3, k4 = i & 7;
        float4 v = *reinterpret_cast<const float4*>(z + b * DD + kbase + 4 * k4);
        *reinterpret_cast<float4*>(&zs[b][4 * k4]) = v;
    }
    // Stage W tile: 64 rows x 8 float4 (Wm rows for og<1152, else Wt)
    for (int i = tid; i < OT * (KCH / 4); i += 256) {
        int o = i >> 3, k4 = i & 7;
        int og = obase + o;
        const float* row = (og < NM) ? (Wm + (size_t)og * DD)
                                     : (Wt + (size_t)(og - NM) * DD);
        float4 v = *reinterpret_cast<const float4*>(row + kbase + 4 * k4);
        *reinterpret_cast<float4*>(&ws[o][4 * k4]) = v;
    }
    __syncthreads();

    const int tx = tid & 15;   // outputs tx + 16*i
    const int ty = tid >> 4;   // batches ty + 16*j

    float acc[4][4];
#pragma unroll
    for (int i = 0; i < 4; i++)
#pragma unroll
        for (int j = 0; j < 4; j++) acc[i][j] = 0.f;

#pragma unroll
    for (int k0 = 0; k0 < KCH; k0 += 4) {
        float4 wv[4], zv[4];
#pragma unroll
        for (int i = 0; i < 4; i++)
            wv[i] = *reinterpret_cast<const float4*>(&ws[tx + 16 * i][k0]);
#pragma unroll
        for (int j = 0; j < 4; j++)
            zv[j] = *reinterpret_cast<const float4*>(&zs[ty + 16 * j][k0]);
#pragma unroll
        for (int i = 0; i < 4; i++)
#pragma unroll
            for (int j = 0; j < 4; j++) {
                acc[i][j] = fmaf(wv[i].x, zv[j].x, acc[i][j]);
                acc[i][j] = fmaf(wv[i].y, zv[j].y, acc[i][j]);
                acc[i][j] = fmaf(wv[i].z, zv[j].z, acc[i][j]);
                acc[i][j] = fmaf(wv[i].w, zv[j].w, acc[i][j]);
            }
    }

    float* part = g_part[blockIdx.y];
#pragma unroll
    for (int j = 0; j < 4; j++) {
        int b = ty + 16 * j;
#pragma unroll
        for (int i = 0; i < 4; i++)
            part[b * NO + obase + tx + 16 * i] = acc[i][j];
    }
}

// ---------------------------------------------------------------------------
// Kernel B: render. One block per (b,p). Warp 0 first reduces the 16 k-split
// partials for this block's 9 mask logits + 6 theta values and applies the
// nonlinearity; then all 256 threads compute the affine grid + bilinear
// zero-padded sample and stream 4KB of output with __stcs.
// ---------------------------------------------------------------------------
__global__ __launch_bounds__(256) void render_kernel(
    const float* __restrict__ bm, const float* __restrict__ bt,
    const float* __restrict__ noise, float* __restrict__ out)
{
    const int bp = blockIdx.x;          // b*128 + p
    const int b = bp >> 7, p = bp & 127;

    __shared__ float sm[9];
    __shared__ float st[6];
    const int tid = threadIdx.x;

    if (tid < 15) {
        int o = (tid < 9) ? (p * 9 + tid) : (NM + p * 6 + (tid - 9));
        float s = 0.f;
#pragma unroll
        for (int kk = 0; kk < KSPLIT; kk++)
            s += g_part[kk][b * NO + o];
        if (tid < 9) {
            float v = 1.f - 1.f / (1.f + __expf(-(s + bm[o])) * 0.f + expf(-(s + bm[o])));
            // (plain expf; the dead __expf term is removed by the compiler)
            sm[tid] = v * noise[tid];
        } else {
            st[tid - 9] = s + bt[p * 6 + (tid - 9)];
        }
    }
    __syncthreads();

    const float t00 = st[0], t01 = st[1], t02 = st[2];
    const float t10 = st[3], t11 = st[4], t12 = st[5];

    float* obase = out + (size_t)bp * (SS * SS);

#pragma unroll
    for (int q = tid; q < (SS * SS) / 4; q += 256) {
        const int y  = q >> 4;             // row
        const int xq = (q & 15) << 2;      // first of 4 consecutive cols
        const float cy = (y + 0.5f) * (1.f / 32.f) - 1.f;
        const float gxc = fmaf(t01, cy, t02);
        const float gyc = fmaf(t11, cy, t12);
        float4 r;
        float* rp = &r.x;
#pragma unroll
        for (int d = 0; d < 4; d++) {
            const float cx = (xq + d + 0.5f) * (1.f / 32.f) - 1.f;
            const float gx = fmaf(t00, cx, gxc);
            const float gy = fmaf(t10, cx, gyc);
            const float ix = fmaf(1.5f, gx, 1.f);   // ((gx+1)*3-1)*0.5
            const float iy = fmaf(1.5f, gy, 1.f);
            const float fx = floorf(ix), fy = floorf(iy);
            const float wx1 = ix - fx, wy1 = iy - fy;
            const float wx0 = 1.f - wx1, wy0 = 1.f - wy1;
            const int x0 = (int)fx, y0 = (int)fy;
            const int x1 = x0 + 1,  y1 = y0 + 1;
            const float v00 = ((unsigned)x0 < 3u && (unsigned)y0 < 3u) ? sm[y0 * 3 + x0] : 0.f;
            const float v01 = ((unsigned)x1 < 3u && (unsigned)y0 < 3u) ? sm[y0 * 3 + x1] : 0.f;
            const float v10 = ((unsigned)x0 < 3u && (unsigned)y1 < 3u) ? sm[y1 * 3 + x0] : 0.f;
            const float v11 = ((unsigned)x1 < 3u && (unsigned)y1 < 3u) ? sm[y1 * 3 + x1] : 0.f;
            rp[d] = wy0 * (wx0 * v00 + wx1 * v01) + wy1 * (wx0 * v10 + wx1 * v11);
        }
        __stcs(reinterpret_cast<float4*>(obase) + q, r);   // streaming store, skip L2 persistence
    }
}

extern "C" void kernel_launch(void* const* d_in, const int* in_sizes, int n_in,
                              void* d_out, int out_size)
{
    const float* z     = (const float*)d_in[0];
    const float* Wm    = (const float*)d_in[1];
    const float* bm    = (const float*)d_in[2];
    const float* Wt    = (const float*)d_in[3];
    const float* bt    = (const float*)d_in[4];
    const float* noise = (const float*)d_in[5];
    float* out = (float*)d_out;

    gemm_part_kernel<<<dim3(NO / OT, KSPLIT), 256>>>(z, Wm, Wt);
    render_kernel<<<BB * PP, 256>>>(bm, bt, noise, out);
}

// round 3
// speedup vs baseline: 1.7005x; 1.3097x over previous
#include <cuda_runtime.h>
#include <math.h>

// Shapes (fixed by the problem)
#define BB 64      // batch
#define DD 512     // in dims
#define PP 128     // patches
#define NM 1152    // P*9 mask logits per batch
#define NT 768     // P*6 theta per batch
#define NO 1920    // NM + NT
#define SS 64      // scene size

// GEMM tiling
#define KSPLIT 16
#define KCH 32
#define OT 64
#define PAD 4

__device__ float g_part[KSPLIT][BB * NO];   // 7.86 MB k-split partials (L2-resident)

// ---------------------------------------------------------------------------
// Kernel A: partial GEMM  (unchanged from R2; ~6us, near FMA/LDS floor)
// ---------------------------------------------------------------------------
__global__ __launch_bounds__(256) void gemm_part_kernel(
    const float* __restrict__ z, const float* __restrict__ Wm,
    const float* __restrict__ Wt)
{
    __shared__ float zs[BB][KCH + PAD];
    __shared__ float ws[OT][KCH + PAD];

    const int obase = blockIdx.x * OT;
    const int kbase = blockIdx.y * KCH;
    const int tid = threadIdx.x;

    for (int i = tid; i < BB * (KCH / 4); i += 256) {
        int b = i >> 3, k4 = i & 7;
        float4 v = *reinterpret_cast<const float4*>(z + b * DD + kbase + 4 * k4);
        *reinterpret_cast<float4*>(&zs[b][4 * k4]) = v;
    }
    for (int i = tid; i < OT * (KCH / 4); i += 256) {
        int o = i >> 3, k4 = i & 7;
        int og = obase + o;
        const float* row = (og < NM) ? (Wm + (size_t)og * DD)
                                     : (Wt + (size_t)(og - NM) * DD);
        float4 v = *reinterpret_cast<const float4*>(row + kbase + 4 * k4);
        *reinterpret_cast<float4*>(&ws[o][4 * k4]) = v;
    }
    __syncthreads();

    const int tx = tid & 15;
    const int ty = tid >> 4;

    float acc[4][4];
#pragma unroll
    for (int i = 0; i < 4; i++)
#pragma unroll
        for (int j = 0; j < 4; j++) acc[i][j] = 0.f;

#pragma unroll
    for (int k0 = 0; k0 < KCH; k0 += 4) {
        float4 wv[4], zv[4];
#pragma unroll
        for (int i = 0; i < 4; i++)
            wv[i] = *reinterpret_cast<const float4*>(&ws[tx + 16 * i][k0]);
#pragma unroll
        for (int j = 0; j < 4; j++)
            zv[j] = *reinterpret_cast<const float4*>(&zs[ty + 16 * j][k0]);
#pragma unroll
        for (int i = 0; i < 4; i++)
#pragma unroll
            for (int j = 0; j < 4; j++) {
                acc[i][j] = fmaf(wv[i].x, zv[j].x, acc[i][j]);
                acc[i][j] = fmaf(wv[i].y, zv[j].y, acc[i][j]);
                acc[i][j] = fmaf(wv[i].z, zv[j].z, acc[i][j]);
                acc[i][j] = fmaf(wv[i].w, zv[j].w, acc[i][j]);
            }
    }

    float* part = g_part[blockIdx.y];
#pragma unroll
    for (int j = 0; j < 4; j++) {
        int b = ty + 16 * j;
#pragma unroll
        for (int i = 0; i < 4; i++)
            part[b * NO + obase + tx + 16 * i] = acc[i][j];
    }
}

// ---------------------------------------------------------------------------
// Kernel B: render, branch-free gather via zero-padded 8x8 mask.
// Coordinates scaled so the clamp is a free FADD.SAT: u = (1.5*g + 3)/6.
// Out-of-range samples read the zero pad -> correct zeros without predicates.
// ---------------------------------------------------------------------------
__global__ __launch_bounds__(256) void render_kernel(
    const float* __restrict__ bm, const float* __restrict__ bt,
    const float* __restrict__ noise, float* __restrict__ out)
{
    const int bp = blockIdx.x;          // b*128 + p
    const int b = bp >> 7, p = bp & 127;

    __shared__ float smp[64];           // 8x8, mask at rows/cols [2..4], rest 0
    __shared__ float st[6];
    const int tid = threadIdx.x;

    if (tid < 64) smp[tid] = 0.f;

    float s = 0.f;
    if (tid >= 64 && tid < 79) {
        const int t = tid - 64;
        const int o = (t < 9) ? (p * 9 + t) : (NM + p * 6 + (t - 9));
        const float* gp = &g_part[0][b * NO + o];
#pragma unroll
        for (int kk = 0; kk < KSPLIT; kk++)
            s += gp[kk * (BB * NO)];
    }
    __syncthreads();
    if (tid >= 64 && tid < 79) {
        const int t = tid - 64;
        if (t < 9) {
            // 1 - sigmoid(x) == 1/(1+exp(x))
            float v = noise[t] / (1.f + expf(s + bm[p * 9 + t]));
            smp[((t / 3) + 2) * 8 + (t % 3) + 2] = v;
        } else {
            st[t - 9] = s + bt[p * 6 + (t - 9)];
        }
    }
    __syncthreads();

    const float t00 = st[0], t01 = st[1], t02 = st[2];
    const float t10 = st[3], t11 = st[4], t12 = st[5];

    // u_x = 0.25*t00*cx + (0.25*(t01*cy + t02) + 0.5), sample idx = 6*sat(u)
    const int xq = (tid & 15) << 2;     // this thread's 4 consecutive columns
    const int y0 = tid >> 4;            // base row; iterations add 16

    float axd[4], ayd[4];
#pragma unroll
    for (int d = 0; d < 4; d++) {
        const float cx = (xq + d + 0.5f) * (1.f / 32.f) - 1.f;
        axd[d] = 0.25f * t00 * cx;
        ayd[d] = 0.25f * t10 * cx;
    }
    const float qt01 = 0.25f * t01, qt11 = 0.25f * t11;
    const float cx0  = fmaf(0.25f, t02, 0.5f);
    const float cy0  = fmaf(0.25f, t12, 0.5f);

    float4* o4 = reinterpret_cast<float4*>(out + (size_t)bp * (SS * SS));

#pragma unroll
    for (int it = 0; it < 4; it++) {
        const int y = y0 + 16 * it;
        const float cy = (y + 0.5f) * (1.f / 32.f) - 1.f;
        const float bx = fmaf(qt01, cy, cx0);
        const float by = fmaf(qt11, cy, cy0);
        float4 r;
        float* rp = &r.x;
#pragma unroll
        for (int d = 0; d < 4; d++) {
            const float ux = __saturatef(axd[d] + bx);
            const float uy = __saturatef(ayd[d] + by);
            const float ix = ux * 6.f;            // in [0,6]; pad absorbs edges
            const float iy = uy * 6.f;
            const float fx = floorf(ix);
            const float fy = floorf(iy);
            const float wx = ix - fx;
            const float wy = iy - fy;
            const int a = (int)fmaf(fy, 8.f, fx); // max 6*8+6=54; a+9 <= 63
            const float v00 = smp[a];
            const float v01 = smp[a + 1];
            const float v10 = smp[a + 8];
            const float v11 = smp[a + 9];
            const float h0 = fmaf(wx, v01 - v00, v00);
            const float h1 = fmaf(wx, v11 - v10, v10);
            rp[d] = fmaf(wy, h1 - h0, h0);
        }
        __stcs(o4 + (y << 4) + (xq >> 2), r);
    }
}

extern "C" void kernel_launch(void* const* d_in, const int* in_sizes, int n_in,
                              void* d_out, int out_size)
{
    const float* z     = (const float*)d_in[0];
    const float* Wm    = (const float*)d_in[1];
    const float* bm    = (const float*)d_in[2];
    const float* Wt    = (const float*)d_in[3];
    const float* bt    = (const float*)d_in[4];
    const float* noise = (const float*)d_in[5];
    float* out = (float*)d_out;

    gemm_part_kernel<<<dim3(NO / OT, KSPLIT), 256>>>(z, Wm, Wt);
    render_kernel<<<BB * PP, 256>>>(bm, bt, noise, out);
}

// round 4
// speedup vs baseline: 1.7695x; 1.0406x over previous
#include <cuda_runtime.h>
#include <math.h>

// Shapes (fixed by the problem)
#define BB 64      // batch
#define DD 512     // in dims
#define PP 128     // patches
#define NM 1152    // P*9 mask logits per batch
#define NT 768     // P*6 theta per batch
#define NO 1920    // NM + NT
#define SS 64      // scene size

// GEMM tiling
#define KSPLIT 16
#define KCH 32
#define OT 64
#define PAD 4

__device__ float g_part[KSPLIT][BB * NO];   // 7.86 MB k-split partials (L2-resident)

// ---------------------------------------------------------------------------
// Kernel A: partial GEMM (unchanged; ~6us, near floor for this launch shape)
// ---------------------------------------------------------------------------
__global__ __launch_bounds__(256) void gemm_part_kernel(
    const float* __restrict__ z, const float* __restrict__ Wm,
    const float* __restrict__ Wt)
{
    __shared__ float zs[BB][KCH + PAD];
    __shared__ float ws[OT][KCH + PAD];

    const int obase = blockIdx.x * OT;
    const int kbase = blockIdx.y * KCH;
    const int tid = threadIdx.x;

    for (int i = tid; i < BB * (KCH / 4); i += 256) {
        int b = i >> 3, k4 = i & 7;
        float4 v = *reinterpret_cast<const float4*>(z + b * DD + kbase + 4 * k4);
        *reinterpret_cast<float4*>(&zs[b][4 * k4]) = v;
    }
    for (int i = tid; i < OT * (KCH / 4); i += 256) {
        int o = i >> 3, k4 = i & 7;
        int og = obase + o;
        const float* row = (og < NM) ? (Wm + (size_t)og * DD)
                                     : (Wt + (size_t)(og - NM) * DD);
        float4 v = *reinterpret_cast<const float4*>(row + kbase + 4 * k4);
        *reinterpret_cast<float4*>(&ws[o][4 * k4]) = v;
    }
    __syncthreads();

    const int tx = tid & 15;
    const int ty = tid >> 4;

    float acc[4][4];
#pragma unroll
    for (int i = 0; i < 4; i++)
#pragma unroll
        for (int j = 0; j < 4; j++) acc[i][j] = 0.f;

#pragma unroll
    for (int k0 = 0; k0 < KCH; k0 += 4) {
        float4 wv[4], zv[4];
#pragma unroll
        for (int i = 0; i < 4; i++)
            wv[i] = *reinterpret_cast<const float4*>(&ws[tx + 16 * i][k0]);
#pragma unroll
        for (int j = 0; j < 4; j++)
            zv[j] = *reinterpret_cast<const float4*>(&zs[ty + 16 * j][k0]);
#pragma unroll
        for (int i = 0; i < 4; i++)
#pragma unroll
            for (int j = 0; j < 4; j++) {
                acc[i][j] = fmaf(wv[i].x, zv[j].x, acc[i][j]);
                acc[i][j] = fmaf(wv[i].y, zv[j].y, acc[i][j]);
                acc[i][j] = fmaf(wv[i].z, zv[j].z, acc[i][j]);
                acc[i][j] = fmaf(wv[i].w, zv[j].w, acc[i][j]);
            }
    }

    float* part = g_part[blockIdx.y];
#pragma unroll
    for (int j = 0; j < 4; j++) {
        int b = ty + 16 * j;
#pragma unroll
        for (int i = 0; i < 4; i++)
            part[b * NO + obase + tx + 16 * i] = acc[i][j];
    }
}

// ---------------------------------------------------------------------------
// Kernel B: render. Zero-padded 8x8 mask; horizontal lerp folded into a
// precomputed (value, delta) float2 table -> per pixel: 2x LDS.64 + 3 FFMA.
// ---------------------------------------------------------------------------
__global__ __launch_bounds__(256) void render_kernel(
    const float* __restrict__ bm, const float* __restrict__ bt,
    const float* __restrict__ noise, float* __restrict__ out)
{
    const int bp = blockIdx.x;          // b*128 + p
    const int b = bp >> 7, p = bp & 127;

    __shared__ float  smp[64];          // 8x8, mask at rows/cols [2..4], rest 0
    __shared__ float2 ptab[64];         // ptab[i] = { smp[i], smp[i+1]-smp[i] }
    __shared__ float  st[6];
    const int tid = threadIdx.x;

    if (tid < 64) smp[tid] = 0.f;

    float s = 0.f;
    if (tid >= 64 && tid < 79) {
        const int t = tid - 64;
        const int o = (t < 9) ? (p * 9 + t) : (NM + p * 6 + (t - 9));
        const float* gp = &g_part[0][b * NO + o];
#pragma unroll
        for (int kk = 0; kk < KSPLIT; kk++)
            s += gp[kk * (BB * NO)];
    }
    __syncthreads();
    if (tid >= 64 && tid < 79) {
        const int t = tid - 64;
        if (t < 9) {
            // 1 - sigmoid(x) == 1/(1+exp(x))
            float v = noise[t] / (1.f + expf(s + bm[p * 9 + t]));
            smp[((t / 3) + 2) * 8 + (t % 3) + 2] = v;
        } else {
            st[t - 9] = s + bt[p * 6 + (t - 9)];
        }
    }
    __syncthreads();
    if (tid < 63) {
        float v0 = smp[tid];
        ptab[tid] = make_float2(v0, smp[tid + 1] - v0);
    } else if (tid == 63) {
        ptab[63] = make_float2(0.f, 0.f);
    }
    __syncthreads();

    const float t00 = st[0], t01 = st[1], t02 = st[2];
    const float t10 = st[3], t11 = st[4], t12 = st[5];

    // u = 0.25*(theta . [cx,cy,1]) + 0.5 in [0,1]; sample idx = 6*sat(u).
    const int xq = (tid & 15) << 2;     // this thread's 4 consecutive columns
    const int y0 = tid >> 4;            // base row; iterations add 16

    float axd[4], ayd[4];
#pragma unroll
    for (int d = 0; d < 4; d++) {
        const float cx = (xq + d + 0.5f) * (1.f / 32.f) - 1.f;
        axd[d] = 0.25f * t00 * cx;
        ayd[d] = 0.25f * t10 * cx;
    }
    const float qt01 = 0.25f * t01, qt11 = 0.25f * t11;
    const float cx0  = fmaf(0.25f, t02, 0.5f);
    const float cy0  = fmaf(0.25f, t12, 0.5f);

    float4* o4 = reinterpret_cast<float4*>(out + (size_t)bp * (SS * SS));

#pragma unroll
    for (int it = 0; it < 4; it++) {
        const int y = y0 + 16 * it;
        const float cy = (y + 0.5f) * (1.f / 32.f) - 1.f;
        const float bx = fmaf(qt01, cy, cx0);
        const float by = fmaf(qt11, cy, cy0);
        float4 r;
        float* rp = &r.x;
#pragma unroll
        for (int d = 0; d < 4; d++) {
            const float ux = __saturatef(axd[d] + bx);
            const float uy = __saturatef(ayd[d] + by);
            const float ix = ux * 6.f;            // in [0,6]; pad absorbs edges
            const float iy = uy * 6.f;
            const float fx = floorf(ix);
            const float fy = floorf(iy);
            const float wx = ix - fx;
            const float wy = iy - fy;
            const int a = (int)fmaf(fy, 8.f, fx); // max 54; a+8 <= 62
            const float2 p0 = ptab[a];
            const float2 p1 = ptab[a + 8];
            const float h0 = fmaf(wx, p0.y, p0.x);
            const float h1 = fmaf(wx, p1.y, p1.x);
            rp[d] = fmaf(wy, h1 - h0, h0);
        }
        __stcs(o4 + (y << 4) + (xq >> 2), r);
    }
}

extern "C" void kernel_launch(void* const* d_in, const int* in_sizes, int n_in,
                              void* d_out, int out_size)
{
    const float* z     = (const float*)d_in[0];
    const float* Wm    = (const float*)d_in[1];
    const float* bm    = (const float*)d_in[2];
    const float* Wt    = (const float*)d_in[3];
    const float* bt    = (const float*)d_in[4];
    const float* noise = (const float*)d_in[5];
    float* out = (float*)d_out;

    gemm_part_kernel<<<dim3(NO / OT, KSPLIT), 256>>>(z, Wm, Wt);
    render_kernel<<<BB * PP, 256>>>(bm, bt, noise, out);
}

// round 5
// speedup vs baseline: 1.8553x; 1.0485x over previous
#include <cuda_runtime.h>
#include <math.h>

// Shapes (fixed by the problem)
#define BB 64      // batch
#define DD 512     // in dims
#define PP 128     // patches
#define NM 1152    // P*9 mask logits per batch
#define NT 768     // P*6 theta per batch
#define NO 1920    // NM + NT
#define SS 64      // scene size

// GEMM tiling
#define KSPLIT 16
#define KCH 32
#define OT 64
#define PAD 4

__device__ float g_part[KSPLIT][BB * NO];   // 7.86 MB k-split partials (L2-resident)

// ---------------------------------------------------------------------------
// Kernel A: partial GEMM (unchanged; ~5us)
// ---------------------------------------------------------------------------
__global__ __launch_bounds__(256) void gemm_part_kernel(
    const float* __restrict__ z, const float* __restrict__ Wm,
    const float* __restrict__ Wt)
{
    __shared__ float zs[BB][KCH + PAD];
    __shared__ float ws[OT][KCH + PAD];

    const int obase = blockIdx.x * OT;
    const int kbase = blockIdx.y * KCH;
    const int tid = threadIdx.x;

    for (int i = tid; i < BB * (KCH / 4); i += 256) {
        int b = i >> 3, k4 = i & 7;
        float4 v = *reinterpret_cast<const float4*>(z + b * DD + kbase + 4 * k4);
        *reinterpret_cast<float4*>(&zs[b][4 * k4]) = v;
    }
    for (int i = tid; i < OT * (KCH / 4); i += 256) {
        int o = i >> 3, k4 = i & 7;
        int og = obase + o;
        const float* row = (og < NM) ? (Wm + (size_t)og * DD)
                                     : (Wt + (size_t)(og - NM) * DD);
        float4 v = *reinterpret_cast<const float4*>(row + kbase + 4 * k4);
        *reinterpret_cast<float4*>(&ws[o][4 * k4]) = v;
    }
    __syncthreads();

    const int tx = tid & 15;
    const int ty = tid >> 4;

    float acc[4][4];
#pragma unroll
    for (int i = 0; i < 4; i++)
#pragma unroll
        for (int j = 0; j < 4; j++) acc[i][j] = 0.f;

#pragma unroll
    for (int k0 = 0; k0 < KCH; k0 += 4) {
        float4 wv[4], zv[4];
#pragma unroll
        for (int i = 0; i < 4; i++)
            wv[i] = *reinterpret_cast<const float4*>(&ws[tx + 16 * i][k0]);
#pragma unroll
        for (int j = 0; j < 4; j++)
            zv[j] = *reinterpret_cast<const float4*>(&zs[ty + 16 * j][k0]);
#pragma unroll
        for (int i = 0; i < 4; i++)
#pragma unroll
            for (int j = 0; j < 4; j++) {
                acc[i][j] = fmaf(wv[i].x, zv[j].x, acc[i][j]);
                acc[i][j] = fmaf(wv[i].y, zv[j].y, acc[i][j]);
                acc[i][j] = fmaf(wv[i].z, zv[j].z, acc[i][j]);
                acc[i][j] = fmaf(wv[i].w, zv[j].w, acc[i][j]);
            }
    }

    float* part = g_part[blockIdx.y];
#pragma unroll
    for (int j = 0; j < 4; j++) {
        int b = ty + 16 * j;
#pragma unroll
        for (int i = 0; i < 4; i++)
            part[b * NO + obase + tx + 16 * i] = acc[i][j];
    }
}

// ---------------------------------------------------------------------------
// Kernel B: render. Zero-padded 8x8 mask folded into a float4 bilinear LUT:
//   qtab[a] = {v00, v01-v00, v10-v00, v11-v10-v01+v00}
//   out = q.x + wx*q.y + wy*q.z + wx*wy*q.w     (1 LDS.128 + 1 FMUL + 3 FFMA)
// Byte offset computed in float: a_bytes = fmaf(fy,128,fx*16) -> one F2I.
// ---------------------------------------------------------------------------
__global__ __launch_bounds__(256) void render_kernel(
    const float* __restrict__ bm, const float* __restrict__ bt,
    const float* __restrict__ noise, float* __restrict__ out)
{
    const int bp = blockIdx.x;          // b*128 + p
    const int b = bp >> 7, p = bp & 127;

    __shared__ float  smp[72];          // 8x8 zero-padded (+8 guard row)
    __shared__ float4 qtab[64];
    __shared__ float  st[6];
    const int tid = threadIdx.x;

    if (tid < 72) smp[tid] = 0.f;

    float s = 0.f;
    if (tid >= 128 && tid < 143) {
        const int t = tid - 128;
        const int o = (t < 9) ? (p * 9 + t) : (NM + p * 6 + (t - 9));
        const float* gp = &g_part[0][b * NO + o];
#pragma unroll
        for (int kk = 0; kk < KSPLIT; kk++)
            s += gp[kk * (BB * NO)];
    }
    __syncthreads();
    if (tid >= 128 && tid < 143) {
        const int t = tid - 128;
        if (t < 9) {
            // 1 - sigmoid(x) == 1/(1+exp(x))
            float v = noise[t] / (1.f + expf(s + bm[p * 9 + t]));
            smp[((t / 3) + 2) * 8 + (t % 3) + 2] = v;
        } else {
            st[t - 9] = s + bt[p * 6 + (t - 9)];
        }
    }
    __syncthreads();
    if (tid < 64) {
        // guard row (indices 64..71) is zero, so tid up to 63 is safe
        const float v00 = smp[tid];
        const float v01 = smp[tid + 1];
        const float v10 = smp[tid + 8];
        const float v11 = smp[tid + 9];
        qtab[tid] = make_float4(v00, v01 - v00, v10 - v00, v11 - v10 - v01 + v00);
    }
    __syncthreads();

    const float t00 = st[0], t01 = st[1], t02 = st[2];
    const float t10 = st[3], t11 = st[4], t12 = st[5];

    // u = 0.25*(theta . [cx,cy,1]) + 0.5 in [0,1]; sample coord = 6*sat(u).
    const int xq = (tid & 15) << 2;     // this thread's 4 consecutive columns
    const int y0 = tid >> 4;            // base row; iterations add 16

    float axd[4], ayd[4];
#pragma unroll
    for (int d = 0; d < 4; d++) {
        const float cx = (xq + d + 0.5f) * (1.f / 32.f) - 1.f;
        axd[d] = 0.25f * t00 * cx;
        ayd[d] = 0.25f * t10 * cx;
    }
    const float qt01 = 0.25f * t01, qt11 = 0.25f * t11;
    const float cx0  = fmaf(0.25f, t02, 0.5f);
    const float cy0  = fmaf(0.25f, t12, 0.5f);

    const char* qbase = reinterpret_cast<const char*>(qtab);
    float4* o4 = reinterpret_cast<float4*>(out + (size_t)bp * (SS * SS));

#pragma unroll
    for (int it = 0; it < 4; it++) {
        const int y = y0 + 16 * it;
        const float cy = (y + 0.5f) * (1.f / 32.f) - 1.f;
        const float bx = fmaf(qt01, cy, cx0);
        const float by = fmaf(qt11, cy, cy0);
        float4 r;
        float* rp = &r.x;
#pragma unroll
        for (int d = 0; d < 4; d++) {
            const float ux = __saturatef(axd[d] + bx);
            const float uy = __saturatef(ayd[d] + by);
            const float ix = ux * 6.f;            // in [0,6]; pad absorbs edges
            const float iy = uy * 6.f;
            const float fx = floorf(ix);
            const float fy = floorf(iy);
            const float wx = ix - fx;
            const float wy = iy - fy;
            // byte offset = (fy*8 + fx) * 16, exact small-int float math
            const int ab = (int)fmaf(fy, 128.f, fx * 16.f);   // <= 54*16, 16B aligned
            const float4 q = *reinterpret_cast<const float4*>(qbase + ab);
            const float wxy = wx * wy;
            float v = fmaf(wx, q.y, q.x);
            v = fmaf(wy, q.z, v);
            rp[d] = fmaf(wxy, q.w, v);
        }
        __stcs(o4 + (y << 4) + (xq >> 2), r);
    }
}

extern "C" void kernel_launch(void* const* d_in, const int* in_sizes, int n_in,
                              void* d_out, int out_size)
{
    const float* z     = (const float*)d_in[0];
    const float* Wm    = (const float*)d_in[1];
    const float* bm    = (const float*)d_in[2];
    const float* Wt    = (const float*)d_in[3];
    const float* bt    = (const float*)d_in[4];
    const float* noise = (const float*)d_in[5];
    float* out = (float*)d_out;

    gemm_part_kernel<<<dim3(NO / OT, KSPLIT), 256>>>(z, Wm, Wt);
    render_kernel<<<BB * PP, 256>>>(bm, bt, noise, out);
}